// round 3
// baseline (speedup 1.0000x reference)
#include <cuda_runtime.h>
#include <cuda_bf16.h>

#define T_LEN 4096
#define HID 10
#define NG 40          // 4*HID
#define EMB 256
#define OUT 50257

// Scratch (no allocation allowed): xg has one pad row for the harmless last prefetch.
__device__ float g_xg[(T_LEN + 1) * NG];
__device__ float g_hs[T_LEN * HID];

// ---------------------------------------------------------------------------
// Kernel A: xg[t][g] = emb[x[t]] . w_ih[g] + b_ih[g] + b_hh[g]
// Block: 256 thr = 8 warps. Each block covers 32 t's (t = blockIdx*32 + lane,
// shared by all warps) ; warp w covers gates {w, w+8, ..., w+32} (5 gates).
// w_ih row is warp-uniform -> LDG broadcast, L1-resident (40KB).
// emb rows: 32 scattered rows per warp, reused across the 5 gates (L1).
// ---------------------------------------------------------------------------
__global__ void xg_kernel(const int* __restrict__ x,
                          const float* __restrict__ emb,
                          const float* __restrict__ w_ih,
                          const float* __restrict__ b_ih,
                          const float* __restrict__ b_hh) {
    const int lane = threadIdx.x & 31;
    const int w    = threadIdx.x >> 5;     // 0..7
    const int t    = blockIdx.x * 32 + lane;

    const float4* erow = reinterpret_cast<const float4*>(emb + (long)x[t] * EMB);

    #pragma unroll
    for (int r = 0; r < 5; ++r) {
        const int g = w + r * 8;
        const float4* wrow = reinterpret_cast<const float4*>(w_ih + g * EMB);
        float a0 = 0.f, a1 = 0.f, a2 = 0.f, a3 = 0.f;
        #pragma unroll 8
        for (int e = 0; e < EMB / 4; ++e) {
            float4 ev = erow[e];
            float4 wv = wrow[e];
            a0 = fmaf(ev.x, wv.x, a0);
            a1 = fmaf(ev.y, wv.y, a1);
            a2 = fmaf(ev.z, wv.z, a2);
            a3 = fmaf(ev.w, wv.w, a3);
        }
        g_xg[t * NG + g] = (a0 + a1) + (a2 + a3) + b_ih[g] + b_hh[g];
    }
}

// ---------------------------------------------------------------------------
// Kernel B: sequential LSTM, 1 block / 1 warp.
// lane k (0..31) computes gate k; lanes 0..7 additionally compute gate 32+k.
// PyTorch gate order in rows: i(0..9) f(10..19) g(20..29) o(30..39).
// Activations: accurate EX2/RCP-based (tanh.approx risks the 1e-3 gate over
// a 4096-step recurrence).
//   unified form: e = expf(ec*z); r = (1-e)/(1+e); a = s1*r + s0
//     tanh   : ec=-2, s1=1,   s0=0
//     sigmoid: ec=-1, s1=0.5, s0=0.5   (since sigmoid(z)=0.5+0.5*tanh(z/2))
// ---------------------------------------------------------------------------
__device__ __forceinline__ float tanh_acc(float z) {
    float e = __expf(-2.0f * z);
    return __fdividef(1.0f - e, 1.0f + e);
}

__global__ void __launch_bounds__(32, 1)
lstm_kernel(const float* __restrict__ w_hh) {
    const int k  = threadIdx.x;        // 0..31
    const int kb = k & 7;              // second-gate index base
    const unsigned M = 0xffffffffu;

    float whA[HID], whB[HID];
    #pragma unroll
    for (int j = 0; j < HID; ++j) {
        whA[j] = w_hh[k * HID + j];            // gate k
        whB[j] = w_hh[(32 + kb) * HID + j];    // gate 32+kb (o-type)
    }

    const bool isTanh = (k >= 20 && k < 30);
    const float ec = isTanh ? -2.0f : -1.0f;
    const float s1 = isTanh ?  1.0f :  0.5f;
    const float s0 = isTanh ?  0.0f :  0.5f;

    float hv[HID];
    #pragma unroll
    for (int j = 0; j < HID; ++j) hv[j] = 0.f;
    float c = 0.f;

    float xgA = g_xg[k];
    float xgB = g_xg[32 + kb];

    for (int t = 0; t < T_LEN; ++t) {
        float zA = xgA, zB = xgB;
        #pragma unroll
        for (int j = 0; j < HID; ++j) {
            zA = fmaf(whA[j], hv[j], zA);
            zB = fmaf(whB[j], hv[j], zB);
        }
        // prefetch next step's gate inputs (off critical path)
        xgA = g_xg[(t + 1) * NG + k];
        xgB = g_xg[(t + 1) * NG + 32 + kb];

        // activations
        float eA = __expf(ec * zA);
        float rA = __fdividef(1.0f - eA, 1.0f + eA);
        float aA = fmaf(s1, rA, s0);              // gate k activated

        float eB = __expf(-zB);
        float rB = __fdividef(1.0f - eB, 1.0f + eB);
        float aB = fmaf(0.5f, rB, 0.5f);          // gate 32+kb activated (sigmoid)

        // redistribute to unit lanes j<10: i_j is local (aA), f/g from lanes
        // 10+j / 20+j, o_j from lane 30+j (aA) for j<2 else lane j-2 (aB).
        float fv = __shfl_sync(M, aA, (k + 10) & 31);
        float gv = __shfl_sync(M, aA, (k + 20) & 31);
        float o1 = __shfl_sync(M, aA, (k + 30) & 31);
        float o2 = __shfl_sync(M, aB, (k + 30) & 31);   // (k-2) mod 32
        float ov = (k < 2) ? o1 : o2;
        float iv = aA;                                  // lane j: gate j = i_j

        c = fmaf(fv, c, iv * gv);
        float h = ov * tanh_acc(c);

        if (k < HID) g_hs[t * HID + k] = h;

        #pragma unroll
        for (int j = 0; j < HID; ++j) hv[j] = __shfl_sync(M, h, j);
    }
}

// ---------------------------------------------------------------------------
// Kernel C: logits[t][o] = hs[t] . W_out[o] + b_out[o]
// Grid: (ceil(50257/1024), 4096/128). Block 256 thr = 8 warps.
// Per thread: 4 output columns o0+{0,32,64,96} (W rows + bias in registers),
// loop over the 128-row t tile with h staged in smem (warp-uniform broadcast).
// Stores: scalar, coalesced per warp (rows are 4B-misaligned since O is odd).
// ---------------------------------------------------------------------------
__global__ void out_kernel(const float* __restrict__ W,
                           const float* __restrict__ b,
                           float* __restrict__ out) {
    const int lane = threadIdx.x & 31;
    const int w    = threadIdx.x >> 5;
    const int o0   = blockIdx.x * 1024 + w * 128 + lane;
    const int t0   = blockIdx.y * 128;

    __shared__ float sh[128 * HID];
    for (int i = threadIdx.x; i < 128 * HID; i += 256)
        sh[i] = g_hs[t0 * HID + i];
    __syncthreads();

    float wr[4][HID], br[4];
    bool  valid[4];
    #pragma unroll
    for (int r = 0; r < 4; ++r) {
        const int o = o0 + 32 * r;
        valid[r] = (o < OUT);
        br[r] = valid[r] ? b[o] : 0.f;
        #pragma unroll
        for (int kk = 0; kk < HID; ++kk)
            wr[r][kk] = valid[r] ? W[o * HID + kk] : 0.f;
    }

    for (int ts = 0; ts < 128; ++ts) {
        float h[HID];
        #pragma unroll
        for (int kk = 0; kk < HID; ++kk) h[kk] = sh[ts * HID + kk];

        const size_t row = (size_t)(t0 + ts) * OUT;
        #pragma unroll
        for (int r = 0; r < 4; ++r) {
            float acc = br[r];
            #pragma unroll
            for (int kk = 0; kk < HID; ++kk)
                acc = fmaf(h[kk], wr[r][kk], acc);
            if (valid[r]) out[row + o0 + 32 * r] = acc;
        }
    }
}

// ---------------------------------------------------------------------------
extern "C" void kernel_launch(void* const* d_in, const int* in_sizes, int n_in,
                              void* d_out, int out_size) {
    const int*   x     = (const int*)  d_in[0];
    const float* emb   = (const float*)d_in[1];
    const float* w_ih  = (const float*)d_in[2];
    const float* w_hh  = (const float*)d_in[3];
    const float* b_ih  = (const float*)d_in[4];
    const float* b_hh  = (const float*)d_in[5];
    const float* W_out = (const float*)d_in[6];
    const float* b_out = (const float*)d_in[7];
    float* out = (float*)d_out;

    xg_kernel<<<T_LEN / 32, 256>>>(x, emb, w_ih, b_ih, b_hh);
    lstm_kernel<<<1, 32>>>(w_hh);
    dim3 grid((OUT + 1023) / 1024, T_LEN / 128);
    out_kernel<<<grid, 256>>>(W_out, b_out, out);
}